// round 2
// baseline (speedup 1.0000x reference)
#include <cuda_runtime.h>
#include <math.h>

// Problem constants
#define Nn   4096
#define Mm   2048
#define IS   128     // INPUT_SIZE
#define XC   129     // x columns (INPUT_SIZE+1)
#define INDIM 257    // 2*I+1
#define QDIM 32
#define CATP 288     // padded concat width (9*32), cols 257..287 are zero
#define KG   8224    // 257*32, K of the gate GEMM (W part)
#define NT   258     // 257 W tiles + 1 bias tile (BK=32)

// Scratch (static device globals; no runtime allocation)
__device__ float g_cat [Nn * CATP];   // concat(x,h) padded, row-major [4096][288]
__device__ float g_cgT [CATP * Mm];   // cg transposed: [i][m]
__device__ float g_cnT [CATP * Mm];   // cn transposed: [i][m]
__device__ float g_r   [Mm * IS];
__device__ float g_u   [Mm * IS];

typedef unsigned long long ull;

__device__ __forceinline__ void fma2(ull &c, ull a, ull b) {
    asm("fma.rn.f32x2 %0, %1, %2, %0;" : "+l"(c) : "l"(a), "l"(b));
}
__device__ __forceinline__ ull pack2(float x, float y) {
    ull r; asm("mov.b64 %0, {%1, %2};" : "=l"(r) : "f"(x), "f"(y)); return r;
}
__device__ __forceinline__ float2 unpack2(ull v) {
    float2 f; asm("mov.b64 {%0, %1}, %2;" : "=f"(f.x), "=f"(f.y) : "l"(v)); return f;
}
__device__ __forceinline__ float sigmoidf_(float v) {
    return 1.0f / (1.0f + expf(-v));
}

// ---------------------------------------------------------------------------
// Pack concat(x,h) -> g_cat [4096][288], zero padded cols
// ---------------------------------------------------------------------------
__global__ void k_pack_cat(const float* __restrict__ x, const float* __restrict__ h) {
    int idx = blockIdx.x * 256 + threadIdx.x;
    if (idx >= Nn * CATP) return;
    int row = idx / CATP;
    int c   = idx - row * CATP;
    float v = 0.0f;
    if (c < XC)        v = x[row * XC + c];
    else if (c < INDIM) v = h[row * IS + (c - XC)];
    g_cat[idx] = v;
}

// ---------------------------------------------------------------------------
// GEMM1: cgT[j][m] = sum_k adj[nodes[m]][k] * cat[k][j]
// grid (9, 16): n0 = bx*32 (288 cols), m0 = by*128 ; 256 threads
// ---------------------------------------------------------------------------
__global__ __launch_bounds__(256) void k_gemm1(const float* __restrict__ adj,
                                               const int* __restrict__ nodes) {
    __shared__ float As[32][136];   // [kk][m], padded rows
    __shared__ float Bs[32][32];    // [kk][n]
    __shared__ int rows[128];

    int t  = threadIdx.x;
    int m0 = blockIdx.y * 128;
    int n0 = blockIdx.x * 32;
    if (t < 128) rows[t] = nodes[m0 + t];
    __syncthreads();

    int w = t >> 5, lane = t & 31;
    int tx = t & 7, ty = t >> 3;   // tx: 8 col-groups *4, ty: 32 row-groups *4

    ull acc[4][2];
#pragma unroll
    for (int r = 0; r < 4; r++) { acc[r][0] = 0ULL; acc[r][1] = 0ULL; }

    for (int k0 = 0; k0 < Nn; k0 += 32) {
        // A tile: warp w loads k-cols [4w,4w+4), lane = row (conflict-free STS)
#pragma unroll
        for (int p = 0; p < 4; p++) {
            int row = lane + 32 * p;
            const float4 v = *(const float4*)&adj[(size_t)rows[row] * Nn + k0 + w * 4];
            As[w * 4 + 0][row] = v.x;
            As[w * 4 + 1][row] = v.y;
            As[w * 4 + 2][row] = v.z;
            As[w * 4 + 3][row] = v.w;
        }
        // B tile: 32x32 from g_cat (coalesced)
        {
            int kk = t >> 3, c4 = t & 7;
            *(float4*)&Bs[kk][c4 * 4] =
                *(const float4*)&g_cat[(size_t)(k0 + kk) * CATP + n0 + c4 * 4];
        }
        __syncthreads();

#pragma unroll
        for (int kk = 0; kk < 32; kk++) {
            float4 a4 = *(const float4*)&As[kk][ty * 4];
            ulonglong2 bb = *(const ulonglong2*)&Bs[kk][tx * 4];
            float av[4] = {a4.x, a4.y, a4.z, a4.w};
#pragma unroll
            for (int r = 0; r < 4; r++) {
                ull ar = pack2(av[r], av[r]);
                fma2(acc[r][0], ar, bb.x);
                fma2(acc[r][1], ar, bb.y);
            }
        }
        __syncthreads();
    }

    // write transposed: g_cgT[col][m]
#pragma unroll
    for (int r = 0; r < 4; r++) {
        float2 c0 = unpack2(acc[r][0]);
        float2 c1 = unpack2(acc[r][1]);
        int m = m0 + ty * 4 + r;
        int c = n0 + tx * 4;
        g_cgT[(size_t)(c + 0) * Mm + m] = c0.x;
        g_cgT[(size_t)(c + 1) * Mm + m] = c0.y;
        g_cgT[(size_t)(c + 2) * Mm + m] = c1.x;
        g_cgT[(size_t)(c + 3) * Mm + m] = c1.y;
    }
}

// ---------------------------------------------------------------------------
// Gates GEMM: r,u together.  out[m,o] = Z[m,:] @ Wflat[:,o] + q@b
// Z[m, d*257+i] = q[m,d]*cg[m,i], built per-tile in smem.
// grid (2, 64): n0 = bx*64, m0 = by*32 ; 256 threads
// ---------------------------------------------------------------------------
__global__ __launch_bounds__(256) void k_gates(const float* __restrict__ q,
                                               const float* __restrict__ Wr,
                                               const float* __restrict__ br,
                                               const float* __restrict__ Wu,
                                               const float* __restrict__ bu) {
    __shared__ float Zs[32][34];
    __shared__ float Wrs[32][64];
    __shared__ float Wus[32][64];
    __shared__ float qs[32][33];

    int t  = threadIdx.x;
    int m0 = blockIdx.y * 32;
    int n0 = blockIdx.x * 64;

#pragma unroll
    for (int p = 0; p < 4; p++) {
        int e = t + 256 * p;
        int m = e >> 5, d = e & 31;
        qs[m][d] = q[(size_t)(m0 + m) * QDIM + d];
    }
    __syncthreads();

    int tx = t & 15, ty = t >> 4;   // tx: 16 col-groups *4, ty: 16 row-groups *2

    ull accr[2][2], accu[2][2];
#pragma unroll
    for (int r = 0; r < 2; r++) {
        accr[r][0] = accr[r][1] = 0ULL;
        accu[r][0] = accu[r][1] = 0ULL;
    }

    for (int tile = 0; tile < NT; tile++) {
        int k0 = tile * 32;
        // Z tile: 32kk x 32m, 4 elems/thread, coalesced read of g_cgT
#pragma unroll
        for (int p = 0; p < 4; p++) {
            int e = t + 256 * p;
            int m = e & 31, kk = e >> 5;
            int k = k0 + kk;
            float v;
            if (tile < 257) {
                int d = k / INDIM;
                int i = k - d * INDIM;
                v = qs[m][d] * g_cgT[(size_t)i * Mm + m0 + m];
            } else {
                v = qs[m][k - KG];
            }
            Zs[kk][m] = v;
        }
        // W tiles (both gates), coalesced float4
#pragma unroll
        for (int p = 0; p < 2; p++) {
            int e = t + 256 * p;
            int kk = e >> 4, c4 = e & 15;
            const float *sR, *sU;
            if (tile < 257) {
                sR = &Wr[(size_t)(k0 + kk) * IS + n0 + c4 * 4];
                sU = &Wu[(size_t)(k0 + kk) * IS + n0 + c4 * 4];
            } else {
                sR = &br[(size_t)kk * IS + n0 + c4 * 4];
                sU = &bu[(size_t)kk * IS + n0 + c4 * 4];
            }
            *(float4*)&Wrs[kk][c4 * 4] = *(const float4*)sR;
            *(float4*)&Wus[kk][c4 * 4] = *(const float4*)sU;
        }
        __syncthreads();

#pragma unroll
        for (int kk = 0; kk < 32; kk++) {
            float2 a2 = *(const float2*)&Zs[kk][ty * 2];
            ulonglong2 brr = *(const ulonglong2*)&Wrs[kk][tx * 4];
            ulonglong2 buu = *(const ulonglong2*)&Wus[kk][tx * 4];
            ull a0 = pack2(a2.x, a2.x);
            ull a1 = pack2(a2.y, a2.y);
            fma2(accr[0][0], a0, brr.x); fma2(accr[0][1], a0, brr.y);
            fma2(accr[1][0], a1, brr.x); fma2(accr[1][1], a1, brr.y);
            fma2(accu[0][0], a0, buu.x); fma2(accu[0][1], a0, buu.y);
            fma2(accu[1][0], a1, buu.x); fma2(accu[1][1], a1, buu.y);
        }
        __syncthreads();
    }

#pragma unroll
    for (int r = 0; r < 2; r++) {
        int m = m0 + ty * 2 + r;
        float2 r0 = unpack2(accr[r][0]), r1 = unpack2(accr[r][1]);
        float2 u0 = unpack2(accu[r][0]), u1 = unpack2(accu[r][1]);
        float vr[4] = {r0.x, r0.y, r1.x, r1.y};
        float vu[4] = {u0.x, u0.y, u1.x, u1.y};
#pragma unroll
        for (int c = 0; c < 4; c++) {
            int col = n0 + tx * 4 + c;
            g_r[(size_t)m * IS + col] = sigmoidf_(vr[c]);
            g_u[(size_t)m * IS + col] = sigmoidf_(vu[c]);
        }
    }
}

// ---------------------------------------------------------------------------
// Pack cnT[i][m]: [x[nm], r*h[nm]] transposed
// ---------------------------------------------------------------------------
__global__ void k_pack_cn(const float* __restrict__ x, const float* __restrict__ h,
                          const int* __restrict__ nodes) {
    int idx = blockIdx.x * 256 + threadIdx.x;
    if (idx >= CATP * Mm) return;
    int i = idx / Mm;
    int m = idx - i * Mm;
    float v = 0.0f;
    if (i < XC) {
        v = x[(size_t)nodes[m] * XC + i];
    } else if (i < INDIM) {
        int j = i - XC;
        v = g_r[(size_t)m * IS + j] * h[(size_t)nodes[m] * IS + j];
    }
    g_cnT[idx] = v;
}

// ---------------------------------------------------------------------------
// Candidate gate + final combine
// grid (2, 64); 256 threads. Same structure as k_gates, single gate.
// ---------------------------------------------------------------------------
__global__ __launch_bounds__(256) void k_final(const float* __restrict__ q,
                                               const float* __restrict__ Wc,
                                               const float* __restrict__ bc,
                                               const float* __restrict__ h,
                                               const int* __restrict__ nodes,
                                               float* __restrict__ out) {
    __shared__ float Zs[32][34];
    __shared__ float Wcs[32][64];
    __shared__ float qs[32][33];

    int t  = threadIdx.x;
    int m0 = blockIdx.y * 32;
    int n0 = blockIdx.x * 64;

#pragma unroll
    for (int p = 0; p < 4; p++) {
        int e = t + 256 * p;
        int m = e >> 5, d = e & 31;
        qs[m][d] = q[(size_t)(m0 + m) * QDIM + d];
    }
    __syncthreads();

    int tx = t & 15, ty = t >> 4;

    ull acc[2][2];
    acc[0][0] = acc[0][1] = acc[1][0] = acc[1][1] = 0ULL;

    for (int tile = 0; tile < NT; tile++) {
        int k0 = tile * 32;
#pragma unroll
        for (int p = 0; p < 4; p++) {
            int e = t + 256 * p;
            int m = e & 31, kk = e >> 5;
            int k = k0 + kk;
            float v;
            if (tile < 257) {
                int d = k / INDIM;
                int i = k - d * INDIM;
                v = qs[m][d] * g_cnT[(size_t)i * Mm + m0 + m];
            } else {
                v = qs[m][k - KG];
            }
            Zs[kk][m] = v;
        }
#pragma unroll
        for (int p = 0; p < 2; p++) {
            int e = t + 256 * p;
            int kk = e >> 4, c4 = e & 15;
            const float* sC = (tile < 257)
                ? &Wc[(size_t)(k0 + kk) * IS + n0 + c4 * 4]
                : &bc[(size_t)kk * IS + n0 + c4 * 4];
            *(float4*)&Wcs[kk][c4 * 4] = *(const float4*)sC;
        }
        __syncthreads();

#pragma unroll
        for (int kk = 0; kk < 32; kk++) {
            float2 a2 = *(const float2*)&Zs[kk][ty * 2];
            ulonglong2 bcc = *(const ulonglong2*)&Wcs[kk][tx * 4];
            ull a0 = pack2(a2.x, a2.x);
            ull a1 = pack2(a2.y, a2.y);
            fma2(acc[0][0], a0, bcc.x); fma2(acc[0][1], a0, bcc.y);
            fma2(acc[1][0], a1, bcc.x); fma2(acc[1][1], a1, bcc.y);
        }
        __syncthreads();
    }

#pragma unroll
    for (int r = 0; r < 2; r++) {
        int m = m0 + ty * 2 + r;
        int nm = nodes[m];
        float2 c0 = unpack2(acc[r][0]), c1 = unpack2(acc[r][1]);
        float v[4] = {c0.x, c0.y, c1.x, c1.y};
#pragma unroll
        for (int c = 0; c < 4; c++) {
            int col = n0 + tx * 4 + c;
            float cand = tanhf(v[c]);
            float uu = g_u[(size_t)m * IS + col];
            float rr = g_r[(size_t)m * IS + col];
            float hv = h[(size_t)nm * IS + col];
            out[(size_t)m * IS + col] = (1.0f - uu) * rr * hv + uu * cand;
        }
    }
}

// ---------------------------------------------------------------------------
// Launch
// Inputs (metadata order): x, h, query_vectors, adj, nodes_ind,
//                          W_u, b_u, W_r, b_r, W_c, b_c
// ---------------------------------------------------------------------------
extern "C" void kernel_launch(void* const* d_in, const int* in_sizes, int n_in,
                              void* d_out, int out_size) {
    const float* x    = (const float*)d_in[0];
    const float* h    = (const float*)d_in[1];
    const float* q    = (const float*)d_in[2];
    const float* adj  = (const float*)d_in[3];
    const int*   nodes= (const int*)  d_in[4];
    const float* Wu   = (const float*)d_in[5];
    const float* bu   = (const float*)d_in[6];
    const float* Wr   = (const float*)d_in[7];
    const float* br   = (const float*)d_in[8];
    const float* Wc   = (const float*)d_in[9];
    const float* bc   = (const float*)d_in[10];
    float* out = (float*)d_out;

    k_pack_cat<<<(Nn * CATP + 255) / 256, 256>>>(x, h);
    k_gemm1<<<dim3(9, 16), 256>>>(adj, nodes);
    k_gates<<<dim3(2, 64), 256>>>(q, Wr, br, Wu, bu);
    k_pack_cn<<<(CATP * Mm + 255) / 256, 256>>>(x, h, nodes);
    k_final<<<dim3(2, 64), 256>>>(q, Wc, bc, h, nodes, out);
}

// round 3
// speedup vs baseline: 1.4692x; 1.4692x over previous
#include <cuda_runtime.h>
#include <math.h>

// Problem constants
#define Nn   4096
#define Mm   2048
#define IS   128     // INPUT_SIZE
#define XC   129     // x columns (INPUT_SIZE+1)
#define INDIM 257    // 2*I+1
#define QDIM 32
#define CATP 288     // padded concat width (9*32), cols 257..287 are zero
#define KG   8224    // 257*32, K of the gate GEMM (W part)
#define NT   258     // 257 W tiles + 1 bias tile (BK=32)

// Split-K factors
#define S_GATE 6     // 258 tiles = 6 * 43
#define TPS    43
#define S_G1   4     // K=4096 -> 4 * 1024

// Scratch (static device globals; no runtime allocation)
__device__ float g_cat [Nn * CATP];           // concat(x,h) padded [4096][288]
__device__ float g_cgT [CATP * Mm];           // cg transposed: [i][m]
__device__ float g_cnT [CATP * Mm];           // cn transposed: [i][m]
__device__ float g_r   [Mm * IS];
__device__ float g_u   [Mm * IS];
__device__ float g_pg1 [S_G1 * CATP * Mm];    // gemm1 partials
__device__ float g_pr  [S_GATE * Mm * IS];    // r partials
__device__ float g_pu  [S_GATE * Mm * IS];    // u partials
__device__ float g_pc  [S_GATE * Mm * IS];    // cand partials

typedef unsigned long long ull;

__device__ __forceinline__ void fma2(ull &c, ull a, ull b) {
    asm("fma.rn.f32x2 %0, %1, %2, %0;" : "+l"(c) : "l"(a), "l"(b));
}
__device__ __forceinline__ ull pack2(float x, float y) {
    ull r; asm("mov.b64 %0, {%1, %2};" : "=l"(r) : "f"(x), "f"(y)); return r;
}
__device__ __forceinline__ float2 unpack2(ull v) {
    float2 f; asm("mov.b64 {%0, %1}, %2;" : "=f"(f.x), "=f"(f.y) : "l"(v)); return f;
}
__device__ __forceinline__ float sigmoidf_(float v) {
    return 1.0f / (1.0f + expf(-v));
}

// ---------------------------------------------------------------------------
// Pack concat(x,h) -> g_cat [4096][288], zero padded cols
// ---------------------------------------------------------------------------
__global__ void k_pack_cat(const float* __restrict__ x, const float* __restrict__ h) {
    int idx = blockIdx.x * 256 + threadIdx.x;
    if (idx >= Nn * CATP) return;
    int row = idx / CATP;
    int c   = idx - row * CATP;
    float v = 0.0f;
    if (c < XC)        v = x[row * XC + c];
    else if (c < INDIM) v = h[row * IS + (c - XC)];
    g_cat[idx] = v;
}

// ---------------------------------------------------------------------------
// GEMM1 (split-K): pg1[s][j][m] = sum_{k in split s} adj[nodes[m]][k]*cat[k][j]
// grid (9, 16, S_G1): n0 = bx*32, m0 = by*128, split = bz ; 256 threads
// ---------------------------------------------------------------------------
__global__ __launch_bounds__(256) void k_gemm1(const float* __restrict__ adj,
                                               const int* __restrict__ nodes) {
    __shared__ float As[32][136];   // [kk][m], padded
    __shared__ float Bs[32][32];    // [kk][n]
    __shared__ int rows[128];

    int t  = threadIdx.x;
    int m0 = blockIdx.y * 128;
    int n0 = blockIdx.x * 32;
    int s  = blockIdx.z;
    if (t < 128) rows[t] = nodes[m0 + t];
    __syncthreads();

    int w = t >> 5, lane = t & 31;
    int tx = t & 7, ty = t >> 3;

    ull acc[4][2];
#pragma unroll
    for (int r = 0; r < 4; r++) { acc[r][0] = 0ULL; acc[r][1] = 0ULL; }

    int kbeg = s * (Nn / S_G1);
    int kend = kbeg + (Nn / S_G1);
    for (int k0 = kbeg; k0 < kend; k0 += 32) {
#pragma unroll
        for (int p = 0; p < 4; p++) {
            int row = lane + 32 * p;
            const float4 v = *(const float4*)&adj[(size_t)rows[row] * Nn + k0 + w * 4];
            As[w * 4 + 0][row] = v.x;
            As[w * 4 + 1][row] = v.y;
            As[w * 4 + 2][row] = v.z;
            As[w * 4 + 3][row] = v.w;
        }
        {
            int kk = t >> 3, c4 = t & 7;
            *(float4*)&Bs[kk][c4 * 4] =
                *(const float4*)&g_cat[(size_t)(k0 + kk) * CATP + n0 + c4 * 4];
        }
        __syncthreads();

#pragma unroll
        for (int kk = 0; kk < 32; kk++) {
            float4 a4 = *(const float4*)&As[kk][ty * 4];
            ulonglong2 bb = *(const ulonglong2*)&Bs[kk][tx * 4];
            float av[4] = {a4.x, a4.y, a4.z, a4.w};
#pragma unroll
            for (int r = 0; r < 4; r++) {
                ull ar = pack2(av[r], av[r]);
                fma2(acc[r][0], ar, bb.x);
                fma2(acc[r][1], ar, bb.y);
            }
        }
        __syncthreads();
    }

    float* dst = &g_pg1[(size_t)s * CATP * Mm];
#pragma unroll
    for (int r = 0; r < 4; r++) {
        float2 c0 = unpack2(acc[r][0]);
        float2 c1 = unpack2(acc[r][1]);
        int m = m0 + ty * 4 + r;
        int c = n0 + tx * 4;
        dst[(size_t)(c + 0) * Mm + m] = c0.x;
        dst[(size_t)(c + 1) * Mm + m] = c0.y;
        dst[(size_t)(c + 2) * Mm + m] = c1.x;
        dst[(size_t)(c + 3) * Mm + m] = c1.y;
    }
}

// reduce gemm1 partials -> g_cgT  (float4 vectorized)
__global__ void k_g1_reduce() {
    int idx = blockIdx.x * 256 + threadIdx.x;
    if (idx >= CATP * Mm / 4) return;
    const float4* p = (const float4*)g_pg1;
    float4 a = p[idx];
    float4 b = p[idx + (CATP * Mm / 4)];
    float4 c = p[idx + 2 * (CATP * Mm / 4)];
    float4 d = p[idx + 3 * (CATP * Mm / 4)];
    float4 o;
    o.x = (a.x + b.x) + (c.x + d.x);
    o.y = (a.y + b.y) + (c.y + d.y);
    o.z = (a.z + b.z) + (c.z + d.z);
    o.w = (a.w + b.w) + (c.w + d.w);
    ((float4*)g_cgT)[idx] = o;
}

// ---------------------------------------------------------------------------
// Gates GEMM (split-K): r,u partials.  Z[m, d*257+i] = q[m,d]*cg[m,i]
// grid (2, 64, S_GATE): n0 = bx*64, m0 = by*32 ; 256 threads
// ---------------------------------------------------------------------------
__global__ __launch_bounds__(256) void k_gates(const float* __restrict__ q,
                                               const float* __restrict__ Wr,
                                               const float* __restrict__ br,
                                               const float* __restrict__ Wu,
                                               const float* __restrict__ bu) {
    __shared__ float Zs[32][34];
    __shared__ float Wrs[32][64];
    __shared__ float Wus[32][64];
    __shared__ float qs[32][33];

    int t  = threadIdx.x;
    int m0 = blockIdx.y * 32;
    int n0 = blockIdx.x * 64;
    int s  = blockIdx.z;

#pragma unroll
    for (int p = 0; p < 4; p++) {
        int e = t + 256 * p;
        int m = e >> 5, d = e & 31;
        qs[m][d] = q[(size_t)(m0 + m) * QDIM + d];
    }
    __syncthreads();

    int tx = t & 15, ty = t >> 4;

    ull accr[2][2], accu[2][2];
#pragma unroll
    for (int r = 0; r < 2; r++) {
        accr[r][0] = accr[r][1] = 0ULL;
        accu[r][0] = accu[r][1] = 0ULL;
    }

    int tbeg = s * TPS, tend = tbeg + TPS;
    for (int tile = tbeg; tile < tend; tile++) {
        int k0 = tile * 32;
#pragma unroll
        for (int p = 0; p < 4; p++) {
            int e = t + 256 * p;
            int m = e & 31, kk = e >> 5;
            int k = k0 + kk;
            float v;
            if (tile < 257) {
                int d = k / INDIM;
                int i = k - d * INDIM;
                v = qs[m][d] * g_cgT[(size_t)i * Mm + m0 + m];
            } else {
                v = qs[m][k - KG];
            }
            Zs[kk][m] = v;
        }
#pragma unroll
        for (int p = 0; p < 2; p++) {
            int e = t + 256 * p;
            int kk = e >> 4, c4 = e & 15;
            const float *sR, *sU;
            if (tile < 257) {
                sR = &Wr[(size_t)(k0 + kk) * IS + n0 + c4 * 4];
                sU = &Wu[(size_t)(k0 + kk) * IS + n0 + c4 * 4];
            } else {
                sR = &br[(size_t)kk * IS + n0 + c4 * 4];
                sU = &bu[(size_t)kk * IS + n0 + c4 * 4];
            }
            *(float4*)&Wrs[kk][c4 * 4] = *(const float4*)sR;
            *(float4*)&Wus[kk][c4 * 4] = *(const float4*)sU;
        }
        __syncthreads();

#pragma unroll
        for (int kk = 0; kk < 32; kk++) {
            float2 a2 = *(const float2*)&Zs[kk][ty * 2];
            ulonglong2 brr = *(const ulonglong2*)&Wrs[kk][tx * 4];
            ulonglong2 buu = *(const ulonglong2*)&Wus[kk][tx * 4];
            ull a0 = pack2(a2.x, a2.x);
            ull a1 = pack2(a2.y, a2.y);
            fma2(accr[0][0], a0, brr.x); fma2(accr[0][1], a0, brr.y);
            fma2(accr[1][0], a1, brr.x); fma2(accr[1][1], a1, brr.y);
            fma2(accu[0][0], a0, buu.x); fma2(accu[0][1], a0, buu.y);
            fma2(accu[1][0], a1, buu.x); fma2(accu[1][1], a1, buu.y);
        }
        __syncthreads();
    }

    float* dr = &g_pr[(size_t)s * Mm * IS];
    float* du = &g_pu[(size_t)s * Mm * IS];
#pragma unroll
    for (int r = 0; r < 2; r++) {
        int m = m0 + ty * 2 + r;
        float2 r0 = unpack2(accr[r][0]), r1 = unpack2(accr[r][1]);
        float2 u0 = unpack2(accu[r][0]), u1 = unpack2(accu[r][1]);
        float4 vr = make_float4(r0.x, r0.y, r1.x, r1.y);
        float4 vu = make_float4(u0.x, u0.y, u1.x, u1.y);
        *(float4*)&dr[(size_t)m * IS + n0 + tx * 4] = vr;
        *(float4*)&du[(size_t)m * IS + n0 + tx * 4] = vu;
    }
}

// reduce gate partials + sigmoid -> g_r, g_u
__global__ void k_gates_reduce() {
    int idx = blockIdx.x * 256 + threadIdx.x;
    if (idx >= Mm * IS / 4) return;
    const float4* pr = (const float4*)g_pr;
    const float4* pu = (const float4*)g_pu;
    float4 r = make_float4(0.f, 0.f, 0.f, 0.f);
    float4 u = make_float4(0.f, 0.f, 0.f, 0.f);
#pragma unroll
    for (int s = 0; s < S_GATE; s++) {
        float4 a = pr[idx + (size_t)s * (Mm * IS / 4)];
        float4 b = pu[idx + (size_t)s * (Mm * IS / 4)];
        r.x += a.x; r.y += a.y; r.z += a.z; r.w += a.w;
        u.x += b.x; u.y += b.y; u.z += b.z; u.w += b.w;
    }
    r.x = sigmoidf_(r.x); r.y = sigmoidf_(r.y); r.z = sigmoidf_(r.z); r.w = sigmoidf_(r.w);
    u.x = sigmoidf_(u.x); u.y = sigmoidf_(u.y); u.z = sigmoidf_(u.z); u.w = sigmoidf_(u.w);
    ((float4*)g_r)[idx] = r;
    ((float4*)g_u)[idx] = u;
}

// ---------------------------------------------------------------------------
// Pack cnT[i][m]: [x[nm], r*h[nm]] transposed
// ---------------------------------------------------------------------------
__global__ void k_pack_cn(const float* __restrict__ x, const float* __restrict__ h,
                          const int* __restrict__ nodes) {
    int idx = blockIdx.x * 256 + threadIdx.x;
    if (idx >= CATP * Mm) return;
    int i = idx / Mm;
    int m = idx - i * Mm;
    float v = 0.0f;
    if (i < XC) {
        v = x[(size_t)nodes[m] * XC + i];
    } else if (i < INDIM) {
        int j = i - XC;
        v = g_r[(size_t)m * IS + j] * h[(size_t)nodes[m] * IS + j];
    }
    g_cnT[idx] = v;
}

// ---------------------------------------------------------------------------
// Candidate GEMM (split-K): partial sums for tanh input
// grid (2, 64, S_GATE); 256 threads
// ---------------------------------------------------------------------------
__global__ __launch_bounds__(256) void k_final(const float* __restrict__ q,
                                               const float* __restrict__ Wc,
                                               const float* __restrict__ bc) {
    __shared__ float Zs[32][34];
    __shared__ float Wcs[32][64];
    __shared__ float qs[32][33];

    int t  = threadIdx.x;
    int m0 = blockIdx.y * 32;
    int n0 = blockIdx.x * 64;
    int s  = blockIdx.z;

#pragma unroll
    for (int p = 0; p < 4; p++) {
        int e = t + 256 * p;
        int m = e >> 5, d = e & 31;
        qs[m][d] = q[(size_t)(m0 + m) * QDIM + d];
    }
    __syncthreads();

    int tx = t & 15, ty = t >> 4;

    ull acc[2][2];
    acc[0][0] = acc[0][1] = acc[1][0] = acc[1][1] = 0ULL;

    int tbeg = s * TPS, tend = tbeg + TPS;
    for (int tile = tbeg; tile < tend; tile++) {
        int k0 = tile * 32;
#pragma unroll
        for (int p = 0; p < 4; p++) {
            int e = t + 256 * p;
            int m = e & 31, kk = e >> 5;
            int k = k0 + kk;
            float v;
            if (tile < 257) {
                int d = k / INDIM;
                int i = k - d * INDIM;
                v = qs[m][d] * g_cnT[(size_t)i * Mm + m0 + m];
            } else {
                v = qs[m][k - KG];
            }
            Zs[kk][m] = v;
        }
#pragma unroll
        for (int p = 0; p < 2; p++) {
            int e = t + 256 * p;
            int kk = e >> 4, c4 = e & 15;
            const float* sC = (tile < 257)
                ? &Wc[(size_t)(k0 + kk) * IS + n0 + c4 * 4]
                : &bc[(size_t)kk * IS + n0 + c4 * 4];
            *(float4*)&Wcs[kk][c4 * 4] = *(const float4*)sC;
        }
        __syncthreads();

#pragma unroll
        for (int kk = 0; kk < 32; kk++) {
            float2 a2 = *(const float2*)&Zs[kk][ty * 2];
            ulonglong2 bcc = *(const ulonglong2*)&Wcs[kk][tx * 4];
            ull a0 = pack2(a2.x, a2.x);
            ull a1 = pack2(a2.y, a2.y);
            fma2(acc[0][0], a0, bcc.x); fma2(acc[0][1], a0, bcc.y);
            fma2(acc[1][0], a1, bcc.x); fma2(acc[1][1], a1, bcc.y);
        }
        __syncthreads();
    }

    float* dc = &g_pc[(size_t)s * Mm * IS];
#pragma unroll
    for (int r = 0; r < 2; r++) {
        int m = m0 + ty * 2 + r;
        float2 c0 = unpack2(acc[r][0]), c1 = unpack2(acc[r][1]);
        float4 v = make_float4(c0.x, c0.y, c1.x, c1.y);
        *(float4*)&dc[(size_t)m * IS + n0 + tx * 4] = v;
    }
}

// reduce candidate partials + tanh + final combine -> out
__global__ void k_final_reduce(const float* __restrict__ h,
                               const int* __restrict__ nodes,
                               float* __restrict__ out) {
    int idx = blockIdx.x * 256 + threadIdx.x;
    if (idx >= Mm * IS / 4) return;
    int m  = idx / (IS / 4);
    int c4 = idx - m * (IS / 4);
    int nm = nodes[m];

    const float4* pc = (const float4*)g_pc;
    float4 c = make_float4(0.f, 0.f, 0.f, 0.f);
#pragma unroll
    for (int s = 0; s < S_GATE; s++) {
        float4 a = pc[idx + (size_t)s * (Mm * IS / 4)];
        c.x += a.x; c.y += a.y; c.z += a.z; c.w += a.w;
    }
    float4 rr = ((const float4*)g_r)[idx];
    float4 uu = ((const float4*)g_u)[idx];
    float4 hv = *(const float4*)&h[(size_t)nm * IS + c4 * 4];
    float4 o;
    o.x = (1.0f - uu.x) * rr.x * hv.x + uu.x * tanhf(c.x);
    o.y = (1.0f - uu.y) * rr.y * hv.y + uu.y * tanhf(c.y);
    o.z = (1.0f - uu.z) * rr.z * hv.z + uu.z * tanhf(c.z);
    o.w = (1.0f - uu.w) * rr.w * hv.w + uu.w * tanhf(c.w);
    *(float4*)&out[(size_t)m * IS + c4 * 4] = o;
}

// ---------------------------------------------------------------------------
// Launch
// Inputs (metadata order): x, h, query_vectors, adj, nodes_ind,
//                          W_u, b_u, W_r, b_r, W_c, b_c
// ---------------------------------------------------------------------------
extern "C" void kernel_launch(void* const* d_in, const int* in_sizes, int n_in,
                              void* d_out, int out_size) {
    const float* x    = (const float*)d_in[0];
    const float* h    = (const float*)d_in[1];
    const float* q    = (const float*)d_in[2];
    const float* adj  = (const float*)d_in[3];
    const int*   nodes= (const int*)  d_in[4];
    const float* Wu   = (const float*)d_in[5];
    const float* bu   = (const float*)d_in[6];
    const float* Wr   = (const float*)d_in[7];
    const float* br   = (const float*)d_in[8];
    const float* Wc   = (const float*)d_in[9];
    const float* bc   = (const float*)d_in[10];
    float* out = (float*)d_out;

    k_pack_cat<<<(Nn * CATP + 255) / 256, 256>>>(x, h);
    k_gemm1<<<dim3(9, 16, S_G1), 256>>>(adj, nodes);
    k_g1_reduce<<<(CATP * Mm / 4 + 255) / 256, 256>>>();
    k_gates<<<dim3(2, 64, S_GATE), 256>>>(q, Wr, br, Wu, bu);
    k_gates_reduce<<<(Mm * IS / 4 + 255) / 256, 256>>>();
    k_pack_cn<<<(CATP * Mm + 255) / 256, 256>>>(x, h, nodes);
    k_final<<<dim3(2, 64, S_GATE), 256>>>(q, Wc, bc);
    k_final_reduce<<<(Mm * IS / 4 + 255) / 256, 256>>>(h, nodes, out);
}

// round 5
// speedup vs baseline: 2.2516x; 1.5325x over previous
#include <cuda_runtime.h>
#include <math.h>
#include <stdint.h>

// Problem constants
#define Nn   4096
#define Mm   2048
#define IS   128
#define XC   129
#define INDIM 257
#define QDIM 32
#define CATP 288
#define KG   8224    // 257*32
#define NT   258     // 257 W tiles + 1 bias tile (BK=32)

#define S_GATE 6     // 258 = 6*43
#define TPS    43
#define S_C    8     // candidate split (uneven, floor-based)
#define S_G1   4

__device__ float g_cat [Nn * CATP];
__device__ float g_cgT [CATP * Mm];
__device__ float g_cnT [CATP * Mm];
__device__ float g_r   [Mm * IS];
__device__ float g_u   [Mm * IS];
__device__ float g_pg1 [S_G1 * CATP * Mm];
__device__ float g_pr  [S_GATE * Mm * IS];
__device__ float g_pu  [S_GATE * Mm * IS];
__device__ float g_pc  [S_C * Mm * IS];

typedef unsigned long long ull;

__device__ __forceinline__ void fma2(ull &c, ull a, ull b) {
    asm("fma.rn.f32x2 %0, %1, %2, %0;" : "+l"(c) : "l"(a), "l"(b));
}
__device__ __forceinline__ ull pack2(float x, float y) {
    ull r; asm("mov.b64 %0, {%1, %2};" : "=l"(r) : "f"(x), "f"(y)); return r;
}
__device__ __forceinline__ float2 unpack2(ull v) {
    float2 f; asm("mov.b64 {%0, %1}, %2;" : "=f"(f.x), "=f"(f.y) : "l"(v)); return f;
}
__device__ __forceinline__ float sigmoidf_(float v) {
    return 1.0f / (1.0f + expf(-v));
}
__device__ __forceinline__ void cpa16(uint32_t dst, const void* src) {
    asm volatile("cp.async.ca.shared.global [%0], [%1], 16;" :: "r"(dst), "l"(src));
}
#define CP_COMMIT() asm volatile("cp.async.commit_group;")
#define CP_WAIT0()  asm volatile("cp.async.wait_group 0;")

// ---------------------------------------------------------------------------
__global__ void k_pack_cat(const float* __restrict__ x, const float* __restrict__ h) {
    int idx = blockIdx.x * 256 + threadIdx.x;
    if (idx >= Nn * CATP) return;
    int row = idx / CATP;
    int c   = idx - row * CATP;
    float v = 0.0f;
    if (c < XC)        v = x[row * XC + c];
    else if (c < INDIM) v = h[row * IS + (c - XC)];
    g_cat[idx] = v;
}

// ---------------------------------------------------------------------------
// GEMM1 (split-K, double-buffered): pg1[s][j][m] = sum_k adj[nodes[m]][k]*cat[k][j]
// BM=64, BN=96, BK=32.  grid (3, 32, S_G1), 256 threads, 4m x 6n per thread.
// ---------------------------------------------------------------------------
__global__ __launch_bounds__(256, 3) void k_gemm1(const float* __restrict__ adj,
                                                  const int* __restrict__ nodes) {
    __shared__ float As[2][32][68];   // [buf][kk][m]; 68 floats = 272B row, 16B-aligned
    __shared__ float Bs[2][32][96];   // [buf][kk][n]
    __shared__ int rows[64];

    int t  = threadIdx.x;
    int m0 = blockIdx.y * 64;
    int n0 = blockIdx.x * 96;
    int s  = blockIdx.z;
    if (t < 64) rows[t] = nodes[m0 + t];
    __syncthreads();

    int w = t >> 5, lane = t & 31;
    int tx = t & 15, ty = t >> 4;

    uint32_t bs_base = (uint32_t)__cvta_generic_to_shared(&Bs[0][0][0]);

    ull acc[4][3];
#pragma unroll
    for (int r = 0; r < 4; r++)
#pragma unroll
        for (int j = 0; j < 3; j++) acc[r][j] = 0ULL;

    const int kbeg = s * (Nn / S_G1);
    const int niter = (Nn / S_G1) / 32;   // 32

    float4 a4[2];
    // ---- stage tile 0 ----
    {
        int k0 = kbeg;
#pragma unroll
        for (int pp = 0; pp < 2; pp++) {
            int row = lane + 32 * pp;
            a4[pp] = *(const float4*)&adj[(size_t)rows[row] * Nn + k0 + w * 4];
        }
#pragma unroll
        for (int p = 0; p < 3; p++) {
            int e = t + 256 * p;
            int row = e / 24, c = e - row * 24;
            cpa16(bs_base + (uint32_t)(row * 384 + c * 16),
                  &g_cat[(size_t)(k0 + row) * CATP + n0 + c * 4]);
        }
        CP_COMMIT();
#pragma unroll
        for (int pp = 0; pp < 2; pp++) {
            int row = lane + 32 * pp;
            As[0][w * 4 + 0][row] = a4[pp].x;
            As[0][w * 4 + 1][row] = a4[pp].y;
            As[0][w * 4 + 2][row] = a4[pp].z;
            As[0][w * 4 + 3][row] = a4[pp].w;
        }
        CP_WAIT0();
        __syncthreads();
    }

    for (int it = 0; it < niter; it++) {
        int buf = it & 1, nb = buf ^ 1;
        bool has = (it + 1 < niter);
        if (has) {
            int k0 = kbeg + (it + 1) * 32;
#pragma unroll
            for (int pp = 0; pp < 2; pp++) {
                int row = lane + 32 * pp;
                a4[pp] = *(const float4*)&adj[(size_t)rows[row] * Nn + k0 + w * 4];
            }
#pragma unroll
            for (int p = 0; p < 3; p++) {
                int e = t + 256 * p;
                int row = e / 24, c = e - row * 24;
                cpa16(bs_base + (uint32_t)(nb * 12288 + row * 384 + c * 16),
                      &g_cat[(size_t)(k0 + row) * CATP + n0 + c * 4]);
            }
            CP_COMMIT();
        }
#pragma unroll
        for (int kk = 0; kk < 32; kk++) {
            float4 a = *(const float4*)&As[buf][kk][ty * 4];
            ull b0 = *(const ull*)&Bs[buf][kk][tx * 6 + 0];
            ull b1 = *(const ull*)&Bs[buf][kk][tx * 6 + 2];
            ull b2 = *(const ull*)&Bs[buf][kk][tx * 6 + 4];
            ull am[4] = {pack2(a.x, a.x), pack2(a.y, a.y), pack2(a.z, a.z), pack2(a.w, a.w)};
#pragma unroll
            for (int r = 0; r < 4; r++) {
                fma2(acc[r][0], am[r], b0);
                fma2(acc[r][1], am[r], b1);
                fma2(acc[r][2], am[r], b2);
            }
        }
        if (has) {
#pragma unroll
            for (int pp = 0; pp < 2; pp++) {
                int row = lane + 32 * pp;
                As[nb][w * 4 + 0][row] = a4[pp].x;
                As[nb][w * 4 + 1][row] = a4[pp].y;
                As[nb][w * 4 + 2][row] = a4[pp].z;
                As[nb][w * 4 + 3][row] = a4[pp].w;
            }
            CP_WAIT0();
        }
        __syncthreads();
    }

    float* dst = &g_pg1[(size_t)s * CATP * Mm];
    int cb = n0 + tx * 6;
#pragma unroll
    for (int r = 0; r < 4; r++) {
        int m = m0 + ty * 4 + r;
#pragma unroll
        for (int j = 0; j < 3; j++) {
            float2 v = unpack2(acc[r][j]);
            dst[(size_t)(cb + 2 * j + 0) * Mm + m] = v.x;
            dst[(size_t)(cb + 2 * j + 1) * Mm + m] = v.y;
        }
    }
}

__global__ void k_g1_reduce() {
    int idx = blockIdx.x * 256 + threadIdx.x;
    if (idx >= CATP * Mm / 4) return;
    const float4* p = (const float4*)g_pg1;
    float4 a = p[idx];
    float4 b = p[idx + (CATP * Mm / 4)];
    float4 c = p[idx + 2 * (CATP * Mm / 4)];
    float4 d = p[idx + 3 * (CATP * Mm / 4)];
    float4 o;
    o.x = (a.x + b.x) + (c.x + d.x);
    o.y = (a.y + b.y) + (c.y + d.y);
    o.z = (a.z + b.z) + (c.z + d.z);
    o.w = (a.w + b.w) + (c.w + d.w);
    ((float4*)g_cgT)[idx] = o;
}

// ---------------------------------------------------------------------------
// Gates GEMM (split-K, double-buffered, dual gate r+u)
// BM=64, BN=64, BK=32. grid (2, 32, S_GATE), 256 threads, 4m x 4n x 2 gates.
// ---------------------------------------------------------------------------
__global__ __launch_bounds__(256, 3) void k_gates(const float* __restrict__ q,
                                                  const float* __restrict__ Wr,
                                                  const float* __restrict__ br,
                                                  const float* __restrict__ Wu,
                                                  const float* __restrict__ bu) {
    __shared__ float qs[64][33];
    __shared__ float Zs[2][32][64];
    __shared__ float Wrs[2][32][64];
    __shared__ float Wus[2][32][64];

    int t  = threadIdx.x;
    int m0 = blockIdx.y * 64;
    int n0 = blockIdx.x * 64;
    int s  = blockIdx.z;

#pragma unroll
    for (int p = 0; p < 8; p++) {
        int e = t + 256 * p;
        int m = e >> 5, d = e & 31;
        qs[m][d] = q[(size_t)(m0 + m) * QDIM + d];
    }
    __syncthreads();

    int tx = t & 15, ty = t >> 4;
    int mloc = t & 63;        // fixed m for Z staging
    int kkb  = t >> 6;        // 0..3

    uint32_t wr_base = (uint32_t)__cvta_generic_to_shared(&Wrs[0][0][0]);
    uint32_t wu_base = (uint32_t)__cvta_generic_to_shared(&Wus[0][0][0]);

    ull accr[4][2], accu[4][2];
#pragma unroll
    for (int r = 0; r < 4; r++) {
        accr[r][0] = accr[r][1] = 0ULL;
        accu[r][0] = accu[r][1] = 0ULL;
    }

    const int tbeg = s * TPS;
    float zreg[8];

#define STAGE_Z(TILE)                                                        \
    {                                                                        \
        int _tile = (TILE);                                                  \
        if (_tile < 257) {                                                   \
            int _k0 = _tile * 32;                                            \
            int _d0 = _k0 / INDIM;                                           \
            int _kb = (_d0 + 1) * INDIM;                                     \
            _Pragma("unroll")                                                \
            for (int p = 0; p < 8; p++) {                                    \
                int _k = _k0 + kkb + 4 * p;                                  \
                int _d = (_k >= _kb) ? _d0 + 1 : _d0;                        \
                int _i = _k - _d * INDIM;                                    \
                zreg[p] = qs[mloc][_d] * g_cgT[(size_t)_i * Mm + m0 + mloc]; \
            }                                                                \
        } else {                                                             \
            _Pragma("unroll")                                                \
            for (int p = 0; p < 8; p++) zreg[p] = qs[mloc][kkb + 4 * p];     \
        }                                                                    \
    }
#define STS_Z(NB)                                                            \
    {                                                                        \
        _Pragma("unroll")                                                    \
        for (int p = 0; p < 8; p++) Zs[NB][kkb + 4 * p][mloc] = zreg[p];     \
    }
#define CPA_W(TILE, NB)                                                      \
    {                                                                        \
        int _tile = (TILE);                                                  \
        int _k0 = _tile * 32;                                                \
        _Pragma("unroll")                                                    \
        for (int p = 0; p < 2; p++) {                                        \
            int e = t + 256 * p;                                             \
            int row = e >> 4, c4 = e & 15;                                   \
            uint32_t off = (uint32_t)((NB) * 8192 + row * 256 + c4 * 16);    \
            if (_tile < 257) {                                               \
                cpa16(wr_base + off, &Wr[(size_t)(_k0 + row) * IS + n0 + c4 * 4]); \
                cpa16(wu_base + off, &Wu[(size_t)(_k0 + row) * IS + n0 + c4 * 4]); \
            } else {                                                         \
                cpa16(wr_base + off, &br[(size_t)row * IS + n0 + c4 * 4]);   \
                cpa16(wu_base + off, &bu[(size_t)row * IS + n0 + c4 * 4]);   \
            }                                                                \
        }                                                                    \
    }

    STAGE_Z(tbeg);
    CPA_W(tbeg, 0);
    CP_COMMIT();
    STS_Z(0);
    CP_WAIT0();
    __syncthreads();

    for (int it = 0; it < TPS; it++) {
        int buf = it & 1, nb = buf ^ 1;
        bool has = (it + 1 < TPS);
        if (has) {
            STAGE_Z(tbeg + it + 1);
            CPA_W(tbeg + it + 1, nb);
            CP_COMMIT();
        }
#pragma unroll
        for (int kk = 0; kk < 32; kk++) {
            float4 a = *(const float4*)&Zs[buf][kk][ty * 4];
            ulonglong2 wr2 = *(const ulonglong2*)&Wrs[buf][kk][tx * 4];
            ulonglong2 wu2 = *(const ulonglong2*)&Wus[buf][kk][tx * 4];
            ull am[4] = {pack2(a.x, a.x), pack2(a.y, a.y), pack2(a.z, a.z), pack2(a.w, a.w)};
#pragma unroll
            for (int r = 0; r < 4; r++) {
                fma2(accr[r][0], am[r], wr2.x);
                fma2(accr[r][1], am[r], wr2.y);
                fma2(accu[r][0], am[r], wu2.x);
                fma2(accu[r][1], am[r], wu2.y);
            }
        }
        if (has) {
            STS_Z(nb);
            CP_WAIT0();
        }
        __syncthreads();
    }

    float* dr = &g_pr[(size_t)s * Mm * IS];
    float* du = &g_pu[(size_t)s * Mm * IS];
#pragma unroll
    for (int r = 0; r < 4; r++) {
        int m = m0 + ty * 4 + r;
        float2 r0 = unpack2(accr[r][0]), r1 = unpack2(accr[r][1]);
        float2 u0 = unpack2(accu[r][0]), u1 = unpack2(accu[r][1]);
        *(float4*)&dr[(size_t)m * IS + n0 + tx * 4] = make_float4(r0.x, r0.y, r1.x, r1.y);
        *(float4*)&du[(size_t)m * IS + n0 + tx * 4] = make_float4(u0.x, u0.y, u1.x, u1.y);
    }
#undef STAGE_Z
#undef STS_Z
#undef CPA_W
}

__global__ void k_gates_reduce() {
    int idx = blockIdx.x * 256 + threadIdx.x;
    if (idx >= Mm * IS / 4) return;
    const float4* pr = (const float4*)g_pr;
    const float4* pu = (const float4*)g_pu;
    float4 r = make_float4(0.f, 0.f, 0.f, 0.f);
    float4 u = make_float4(0.f, 0.f, 0.f, 0.f);
#pragma unroll
    for (int s = 0; s < S_GATE; s++) {
        float4 a = pr[idx + (size_t)s * (Mm * IS / 4)];
        float4 b = pu[idx + (size_t)s * (Mm * IS / 4)];
        r.x += a.x; r.y += a.y; r.z += a.z; r.w += a.w;
        u.x += b.x; u.y += b.y; u.z += b.z; u.w += b.w;
    }
    r.x = sigmoidf_(r.x); r.y = sigmoidf_(r.y); r.z = sigmoidf_(r.z); r.w = sigmoidf_(r.w);
    u.x = sigmoidf_(u.x); u.y = sigmoidf_(u.y); u.z = sigmoidf_(u.z); u.w = sigmoidf_(u.w);
    ((float4*)g_r)[idx] = r;
    ((float4*)g_u)[idx] = u;
}

// ---------------------------------------------------------------------------
__global__ void k_pack_cn(const float* __restrict__ x, const float* __restrict__ h,
                          const int* __restrict__ nodes) {
    int idx = blockIdx.x * 256 + threadIdx.x;
    if (idx >= CATP * Mm) return;
    int i = idx / Mm;
    int m = idx - i * Mm;
    float v = 0.0f;
    if (i < XC) {
        v = x[(size_t)nodes[m] * XC + i];
    } else if (i < INDIM) {
        int j = i - XC;
        v = g_r[(size_t)m * IS + j] * h[(size_t)nodes[m] * IS + j];
    }
    g_cnT[idx] = v;
}

// ---------------------------------------------------------------------------
// Candidate GEMM (split-K, double-buffered, single gate)
// BM=64, BN=64, BK=32. grid (2, 32, S_C), 256 threads, 4m x 4n.
// ---------------------------------------------------------------------------
__global__ __launch_bounds__(256, 4) void k_final(const float* __restrict__ q,
                                                  const float* __restrict__ Wc,
                                                  const float* __restrict__ bc) {
    __shared__ float qs[64][33];
    __shared__ float Zs[2][32][64];
    __shared__ float Wcs[2][32][64];

    int t  = threadIdx.x;
    int m0 = blockIdx.y * 64;
    int n0 = blockIdx.x * 64;
    int s  = blockIdx.z;

#pragma unroll
    for (int p = 0; p < 8; p++) {
        int e = t + 256 * p;
        int m = e >> 5, d = e & 31;
        qs[m][d] = q[(size_t)(m0 + m) * QDIM + d];
    }
    __syncthreads();

    int tx = t & 15, ty = t >> 4;
    int mloc = t & 63;
    int kkb  = t >> 6;

    uint32_t wc_base = (uint32_t)__cvta_generic_to_shared(&Wcs[0][0][0]);

    ull acc[4][2];
#pragma unroll
    for (int r = 0; r < 4; r++) acc[r][0] = acc[r][1] = 0ULL;

    const int tbeg = (s * NT) / S_C;
    const int tend = ((s + 1) * NT) / S_C;
    const int nt_loc = tend - tbeg;
    float zreg[8];

#define STAGE_ZC(TILE)                                                       \
    {                                                                        \
        int _tile = (TILE);                                                  \
        if (_tile < 257) {                                                   \
            int _k0 = _tile * 32;                                            \
            int _d0 = _k0 / INDIM;                                           \
            int _kb = (_d0 + 1) * INDIM;                                     \
            _Pragma("unroll")                                                \
            for (int p = 0; p < 8; p++) {                                    \
                int _k = _k0 + kkb + 4 * p;                                  \
                int _d = (_k >= _kb) ? _d0 + 1 : _d0;                        \
                int _i = _k - _d * INDIM;                                    \
                zreg[p] = qs[mloc][_d] * g_cnT[(size_t)_i * Mm + m0 + mloc]; \
            }                                                                \
        } else {                                                             \
            _Pragma("unroll")                                                \
            for (int p = 0; p < 8; p++) zreg[p] = qs[mloc][kkb + 4 * p];     \
        }                                                                    \
    }
#define STS_ZC(NB)                                                           \
    {                                                                        \
        _Pragma("unroll")                                                    \
        for (int p = 0; p < 8; p++) Zs[NB][kkb + 4 * p][mloc] = zreg[p];     \
    }
#define CPA_WC(TILE, NB)                                                     \
    {                                                                        \
        int _tile = (TILE);                                                  \
        int _k0 = _tile * 32;                                                \
        _Pragma("unroll")                                                    \
        for (int p = 0; p < 2; p++) {                                        \
            int e = t + 256 * p;                                             \
            int row = e >> 4, c4 = e & 15;                                   \
            uint32_t off = (uint32_t)((NB) * 8192 + row * 256 + c4 * 16);    \
            if (_tile < 257)                                                 \
                cpa16(wc_base + off, &Wc[(size_t)(_k0 + row) * IS + n0 + c4 * 4]); \
            else                                                             \
                cpa16(wc_base + off, &bc[(size_t)row * IS + n0 + c4 * 4]);   \
        }                                                                    \
    }

    STAGE_ZC(tbeg);
    CPA_WC(tbeg, 0);
    CP_COMMIT();
    STS_ZC(0);
    CP_WAIT0();
    __syncthreads();

    for (int it = 0; it < nt_loc; it++) {
        int buf = it & 1, nb = buf ^ 1;
        bool has = (it + 1 < nt_loc);
        if (has) {
            STAGE_ZC(tbeg + it + 1);
            CPA_WC(tbeg + it + 1, nb);
            CP_COMMIT();
        }
#pragma unroll
        for (int kk = 0; kk < 32; kk++) {
            float4 a = *(const float4*)&Zs[buf][kk][ty * 4];
            ulonglong2 wc2 = *(const ulonglong2*)&Wcs[buf][kk][tx * 4];
            ull am[4] = {pack2(a.x, a.x), pack2(a.y, a.y), pack2(a.z, a.z), pack2(a.w, a.w)};
#pragma unroll
            for (int r = 0; r < 4; r++) {
                fma2(acc[r][0], am[r], wc2.x);
                fma2(acc[r][1], am[r], wc2.y);
            }
        }
        if (has) {
            STS_ZC(nb);
            CP_WAIT0();
        }
        __syncthreads();
    }

    float* dc = &g_pc[(size_t)s * Mm * IS];
#pragma unroll
    for (int r = 0; r < 4; r++) {
        int m = m0 + ty * 4 + r;
        float2 c0 = unpack2(acc[r][0]), c1 = unpack2(acc[r][1]);
        *(float4*)&dc[(size_t)m * IS + n0 + tx * 4] = make_float4(c0.x, c0.y, c1.x, c1.y);
    }
#undef STAGE_ZC
#undef STS_ZC
#undef CPA_WC
}

__global__ void k_final_reduce(const float* __restrict__ h,
                               const int* __restrict__ nodes,
                               float* __restrict__ out) {
    int idx = blockIdx.x * 256 + threadIdx.x;
    if (idx >= Mm * IS / 4) return;
    int m  = idx / (IS / 4);
    int c4 = idx - m * (IS / 4);
    int nm = nodes[m];

    const float4* pc = (const float4*)g_pc;
    float4 c = make_float4(0.f, 0.f, 0.f, 0.f);
#pragma unroll
    for (int s = 0; s < S_C; s++) {
        float4 a = pc[idx + (size_t)s * (Mm * IS / 4)];
        c.x += a.x; c.y += a.y; c.z += a.z; c.w += a.w;
    }
    float4 rr = ((const float4*)g_r)[idx];
    float4 uu = ((const float4*)g_u)[idx];
    float4 hv = *(const float4*)&h[(size_t)nm * IS + c4 * 4];
    float4 o;
    o.x = (1.0f - uu.x) * rr.x * hv.x + uu.x * tanhf(c.x);
    o.y = (1.0f - uu.y) * rr.y * hv.y + uu.y * tanhf(c.y);
    o.z = (1.0f - uu.z) * rr.z * hv.z + uu.z * tanhf(c.z);
    o.w = (1.0f - uu.w) * rr.w * hv.w + uu.w * tanhf(c.w);
    *(float4*)&out[(size_t)m * IS + c4 * 4] = o;
}

// ---------------------------------------------------------------------------
extern "C" void kernel_launch(void* const* d_in, const int* in_sizes, int n_in,
                              void* d_out, int out_size) {
    const float* x    = (const float*)d_in[0];
    const float* h    = (const float*)d_in[1];
    const float* q    = (const float*)d_in[2];
    const float* adj  = (const float*)d_in[3];
    const int*   nodes= (const int*)  d_in[4];
    const float* Wu   = (const float*)d_in[5];
    const float* bu   = (const float*)d_in[6];
    const float* Wr   = (const float*)d_in[7];
    const float* br   = (const float*)d_in[8];
    const float* Wc   = (const float*)d_in[9];
    const float* bc   = (const float*)d_in[10];
    float* out = (float*)d_out;

    k_pack_cat<<<(Nn * CATP + 255) / 256, 256>>>(x, h);
    k_gemm1<<<dim3(3, 32, S_G1), 256>>>(adj, nodes);
    k_g1_reduce<<<(CATP * Mm / 4 + 255) / 256, 256>>>();
    k_gates<<<dim3(2, 32, S_GATE), 256>>>(q, Wr, br, Wu, bu);
    k_gates_reduce<<<(Mm * IS / 4 + 255) / 256, 256>>>();
    k_pack_cn<<<(CATP * Mm + 255) / 256, 256>>>(x, h, nodes);
    k_final<<<dim3(2, 32, S_C), 256>>>(q, Wc, bc);
    k_final_reduce<<<(Mm * IS / 4 + 255) / 256, 256>>>(h, nodes, out);
}

// round 6
// speedup vs baseline: 2.4313x; 1.0798x over previous
#include <cuda_runtime.h>
#include <math.h>
#include <stdint.h>

// Problem constants
#define Nn   4096
#define Mm   2048
#define IS   128
#define XC   129
#define INDIM 257
#define QDIM 32
#define CATP 288
#define KG   8224
#define NT   258

#define S_GATE 12
#define S_C    24
#define S_G1   8

__device__ float g_cat [Nn * CATP];
__device__ float g_cgT [CATP * Mm];
__device__ float g_cnT [CATP * Mm];
__device__ float g_r   [Mm * IS];
__device__ float g_u   [Mm * IS];
__device__ float g_pg1 [S_G1 * CATP * Mm];
__device__ float g_pr  [S_GATE * Mm * IS];
__device__ float g_pu  [S_GATE * Mm * IS];
__device__ float g_pc  [S_C * Mm * IS];

typedef unsigned long long ull;

__device__ __forceinline__ void fma2(ull &c, ull a, ull b) {
    asm("fma.rn.f32x2 %0, %1, %2, %0;" : "+l"(c) : "l"(a), "l"(b));
}
__device__ __forceinline__ ull pack2(float x, float y) {
    ull r; asm("mov.b64 %0, {%1, %2};" : "=l"(r) : "f"(x), "f"(y)); return r;
}
__device__ __forceinline__ float2 unpack2(ull v) {
    float2 f; asm("mov.b64 {%0, %1}, %2;" : "=f"(f.x), "=f"(f.y) : "l"(v)); return f;
}
__device__ __forceinline__ float sigmoidf_(float v) {
    return 1.0f / (1.0f + expf(-v));
}
__device__ __forceinline__ void cpa16(uint32_t dst, const void* src) {
    asm volatile("cp.async.ca.shared.global [%0], [%1], 16;" :: "r"(dst), "l"(src));
}
#define CP_COMMIT() asm volatile("cp.async.commit_group;")
#define CP_WAIT0()  asm volatile("cp.async.wait_group 0;")

// ---------------------------------------------------------------------------
__global__ void k_pack_cat(const float* __restrict__ x, const float* __restrict__ h) {
    int idx = blockIdx.x * 256 + threadIdx.x;
    if (idx >= Nn * CATP) return;
    int row = idx / CATP;
    int c   = idx - row * CATP;
    float v = 0.0f;
    if (c < XC)        v = x[row * XC + c];
    else if (c < INDIM) v = h[row * IS + (c - XC)];
    g_cat[idx] = v;
}

// ---------------------------------------------------------------------------
// GEMM1: BM=128, BN=96, BK=32. grid (3, 16, S_G1), 256 thr, 8m x 6n.
// ---------------------------------------------------------------------------
__global__ __launch_bounds__(256, 2) void k_gemm1(const float* __restrict__ adj,
                                                  const int* __restrict__ nodes) {
    __shared__ float As[2][32][132];   // row = 528B, 16B-aligned
    __shared__ float Bs[2][32][96];    // row = 384B
    __shared__ int rows[128];

    int t  = threadIdx.x;
    int m0 = blockIdx.y * 128;
    int n0 = blockIdx.x * 96;
    int s  = blockIdx.z;
    if (t < 128) rows[t] = nodes[m0 + t];
    __syncthreads();

    int w = t >> 5, lane = t & 31;
    int tx = t & 15, ty = t >> 4;

    uint32_t bs_base = (uint32_t)__cvta_generic_to_shared(&Bs[0][0][0]);

    ull acc[8][3];
#pragma unroll
    for (int r = 0; r < 8; r++)
#pragma unroll
        for (int j = 0; j < 3; j++) acc[r][j] = 0ULL;

    const int kbeg = s * (Nn / S_G1);
    const int niter = (Nn / S_G1) / 32;   // 16

    float4 a4[4];
#define G1_LDA(K0)                                                            \
    _Pragma("unroll")                                                         \
    for (int pp = 0; pp < 4; pp++) {                                          \
        int row = lane + 32 * pp;                                             \
        a4[pp] = *(const float4*)&adj[(size_t)rows[row] * Nn + (K0) + w * 4]; \
    }
#define G1_STA(NB)                                                            \
    _Pragma("unroll")                                                         \
    for (int pp = 0; pp < 4; pp++) {                                          \
        int row = lane + 32 * pp;                                             \
        As[NB][w * 4 + 0][row] = a4[pp].x;                                    \
        As[NB][w * 4 + 1][row] = a4[pp].y;                                    \
        As[NB][w * 4 + 2][row] = a4[pp].z;                                    \
        As[NB][w * 4 + 3][row] = a4[pp].w;                                    \
    }
#define G1_LDB(K0, NB)                                                        \
    _Pragma("unroll")                                                         \
    for (int p = 0; p < 3; p++) {                                             \
        int e = t + 256 * p;                                                  \
        int row = e / 24, c = e - row * 24;                                   \
        cpa16(bs_base + (uint32_t)((NB) * 12288 + row * 384 + c * 16),        \
              &g_cat[(size_t)((K0) + row) * CATP + n0 + c * 4]);              \
    }

    G1_LDA(kbeg);
    G1_LDB(kbeg, 0);
    CP_COMMIT();
    G1_STA(0);
    CP_WAIT0();
    __syncthreads();

    for (int it = 0; it < niter; it++) {
        int buf = it & 1, nb = buf ^ 1;
        bool has = (it + 1 < niter);
        if (has) {
            int k0 = kbeg + (it + 1) * 32;
            G1_LDA(k0);
            G1_LDB(k0, nb);
            CP_COMMIT();
        }
#pragma unroll
        for (int kk = 0; kk < 32; kk++) {
            float4 a0 = *(const float4*)&As[buf][kk][ty * 8];
            float4 a1 = *(const float4*)&As[buf][kk][ty * 8 + 4];
            ull b0 = *(const ull*)&Bs[buf][kk][tx * 6 + 0];
            ull b1 = *(const ull*)&Bs[buf][kk][tx * 6 + 2];
            ull b2 = *(const ull*)&Bs[buf][kk][tx * 6 + 4];
            float av[8] = {a0.x, a0.y, a0.z, a0.w, a1.x, a1.y, a1.z, a1.w};
#pragma unroll
            for (int r = 0; r < 8; r++) {
                ull am = pack2(av[r], av[r]);
                fma2(acc[r][0], am, b0);
                fma2(acc[r][1], am, b1);
                fma2(acc[r][2], am, b2);
            }
        }
        if (has) {
            G1_STA(nb);
            CP_WAIT0();
        }
        __syncthreads();
    }

    float* dst = &g_pg1[(size_t)s * CATP * Mm];
    int cb = n0 + tx * 6;
#pragma unroll
    for (int r = 0; r < 8; r++) {
        int m = m0 + ty * 8 + r;
#pragma unroll
        for (int j = 0; j < 3; j++) {
            float2 v = unpack2(acc[r][j]);
            dst[(size_t)(cb + 2 * j + 0) * Mm + m] = v.x;
            dst[(size_t)(cb + 2 * j + 1) * Mm + m] = v.y;
        }
    }
#undef G1_LDA
#undef G1_STA
#undef G1_LDB
}

__global__ void k_g1_reduce() {
    int idx = blockIdx.x * 256 + threadIdx.x;
    if (idx >= CATP * Mm / 4) return;
    const float4* p = (const float4*)g_pg1;
    float4 o = make_float4(0.f, 0.f, 0.f, 0.f);
#pragma unroll
    for (int s = 0; s < S_G1; s++) {
        float4 a = p[idx + (size_t)s * (CATP * Mm / 4)];
        o.x += a.x; o.y += a.y; o.z += a.z; o.w += a.w;
    }
    ((float4*)g_cgT)[idx] = o;
}

// ---------------------------------------------------------------------------
// Gates GEMM: BM=128, BN=64, BK=32. grid (2, 16, S_GATE), 256 thr, 8m x 4n x 2.
// ---------------------------------------------------------------------------
__global__ __launch_bounds__(256, 2) void k_gates(const float* __restrict__ q,
                                                  const float* __restrict__ Wr,
                                                  const float* __restrict__ br,
                                                  const float* __restrict__ Wu,
                                                  const float* __restrict__ bu) {
    __shared__ float qs[128][33];
    __shared__ float Zs[2][32][128];   // row = 512B
    __shared__ float Wrs[2][32][64];   // row = 256B
    __shared__ float Wus[2][32][64];

    int t  = threadIdx.x;
    int m0 = blockIdx.y * 128;
    int n0 = blockIdx.x * 64;
    int s  = blockIdx.z;

#pragma unroll
    for (int p = 0; p < 16; p++) {
        int e = t + 256 * p;
        int m = e >> 5, d = e & 31;
        qs[m][d] = q[(size_t)(m0 + m) * QDIM + d];
    }
    __syncthreads();

    int tx = t & 15, ty = t >> 4;
    int mloc = t & 127;       // staging m
    int kkb  = t >> 7;        // 0..1

    uint32_t wr_base = (uint32_t)__cvta_generic_to_shared(&Wrs[0][0][0]);
    uint32_t wu_base = (uint32_t)__cvta_generic_to_shared(&Wus[0][0][0]);

    ull accr[8][2], accu[8][2];
#pragma unroll
    for (int r = 0; r < 8; r++) {
        accr[r][0] = accr[r][1] = 0ULL;
        accu[r][0] = accu[r][1] = 0ULL;
    }

    const int tbeg = (s * NT) / S_GATE;
    const int tend = ((s + 1) * NT) / S_GATE;
    const int nt_loc = tend - tbeg;
    float zreg[16];

#define STAGE_Z(TILE, SRC)                                                   \
    {                                                                        \
        int _tile = (TILE);                                                  \
        if (_tile < 257) {                                                   \
            int _k0 = _tile * 32;                                            \
            int _d0 = _k0 / INDIM;                                           \
            int _kb = (_d0 + 1) * INDIM;                                     \
            _Pragma("unroll")                                                \
            for (int p = 0; p < 16; p++) {                                   \
                int _k = _k0 + kkb + 2 * p;                                  \
                int _d = (_k >= _kb) ? _d0 + 1 : _d0;                        \
                int _i = _k - _d * INDIM;                                    \
                zreg[p] = qs[mloc][_d] * SRC[(size_t)_i * Mm + m0 + mloc];   \
            }                                                                \
        } else {                                                             \
            _Pragma("unroll")                                                \
            for (int p = 0; p < 16; p++) zreg[p] = qs[mloc][kkb + 2 * p];    \
        }                                                                    \
    }
#define STS_Z(NB)                                                            \
    {                                                                        \
        _Pragma("unroll")                                                    \
        for (int p = 0; p < 16; p++) Zs[NB][kkb + 2 * p][mloc] = zreg[p];    \
    }
#define CPA_W(TILE, NB)                                                      \
    {                                                                        \
        int _tile = (TILE);                                                  \
        int _k0 = _tile * 32;                                                \
        _Pragma("unroll")                                                    \
        for (int p = 0; p < 2; p++) {                                        \
            int e = t + 256 * p;                                             \
            int row = e >> 4, c4 = e & 15;                                   \
            uint32_t off = (uint32_t)((NB) * 8192 + row * 256 + c4 * 16);    \
            if (_tile < 257) {                                               \
                cpa16(wr_base + off, &Wr[(size_t)(_k0 + row) * IS + n0 + c4 * 4]); \
                cpa16(wu_base + off, &Wu[(size_t)(_k0 + row) * IS + n0 + c4 * 4]); \
            } else {                                                         \
                cpa16(wr_base + off, &br[(size_t)row * IS + n0 + c4 * 4]);   \
                cpa16(wu_base + off, &bu[(size_t)row * IS + n0 + c4 * 4]);   \
            }                                                                \
        }                                                                    \
    }

    STAGE_Z(tbeg, g_cgT);
    CPA_W(tbeg, 0);
    CP_COMMIT();
    STS_Z(0);
    CP_WAIT0();
    __syncthreads();

    for (int it = 0; it < nt_loc; it++) {
        int buf = it & 1, nb = buf ^ 1;
        bool has = (it + 1 < nt_loc);
        if (has) {
            STAGE_Z(tbeg + it + 1, g_cgT);
            CPA_W(tbeg + it + 1, nb);
            CP_COMMIT();
        }
#pragma unroll
        for (int kk = 0; kk < 32; kk++) {
            float4 z0 = *(const float4*)&Zs[buf][kk][ty * 8];
            float4 z1 = *(const float4*)&Zs[buf][kk][ty * 8 + 4];
            ulonglong2 wr2 = *(const ulonglong2*)&Wrs[buf][kk][tx * 4];
            ulonglong2 wu2 = *(const ulonglong2*)&Wus[buf][kk][tx * 4];
            float zv[8] = {z0.x, z0.y, z0.z, z0.w, z1.x, z1.y, z1.z, z1.w};
#pragma unroll
            for (int r = 0; r < 8; r++) {
                ull am = pack2(zv[r], zv[r]);
                fma2(accr[r][0], am, wr2.x);
                fma2(accr[r][1], am, wr2.y);
                fma2(accu[r][0], am, wu2.x);
                fma2(accu[r][1], am, wu2.y);
            }
        }
        if (has) {
            STS_Z(nb);
            CP_WAIT0();
        }
        __syncthreads();
    }

    float* dr = &g_pr[(size_t)s * Mm * IS];
    float* du = &g_pu[(size_t)s * Mm * IS];
#pragma unroll
    for (int r = 0; r < 8; r++) {
        int m = m0 + ty * 8 + r;
        float2 r0 = unpack2(accr[r][0]), r1 = unpack2(accr[r][1]);
        float2 u0 = unpack2(accu[r][0]), u1 = unpack2(accu[r][1]);
        *(float4*)&dr[(size_t)m * IS + n0 + tx * 4] = make_float4(r0.x, r0.y, r1.x, r1.y);
        *(float4*)&du[(size_t)m * IS + n0 + tx * 4] = make_float4(u0.x, u0.y, u1.x, u1.y);
    }
}

__global__ void k_gates_reduce() {
    int idx = blockIdx.x * 256 + threadIdx.x;
    if (idx >= Mm * IS / 4) return;
    const float4* pr = (const float4*)g_pr;
    const float4* pu = (const float4*)g_pu;
    float4 r = make_float4(0.f, 0.f, 0.f, 0.f);
    float4 u = make_float4(0.f, 0.f, 0.f, 0.f);
#pragma unroll
    for (int s = 0; s < S_GATE; s++) {
        float4 a = pr[idx + (size_t)s * (Mm * IS / 4)];
        float4 b = pu[idx + (size_t)s * (Mm * IS / 4)];
        r.x += a.x; r.y += a.y; r.z += a.z; r.w += a.w;
        u.x += b.x; u.y += b.y; u.z += b.z; u.w += b.w;
    }
    r.x = sigmoidf_(r.x); r.y = sigmoidf_(r.y); r.z = sigmoidf_(r.z); r.w = sigmoidf_(r.w);
    u.x = sigmoidf_(u.x); u.y = sigmoidf_(u.y); u.z = sigmoidf_(u.z); u.w = sigmoidf_(u.w);
    ((float4*)g_r)[idx] = r;
    ((float4*)g_u)[idx] = u;
}

// ---------------------------------------------------------------------------
__global__ void k_pack_cn(const float* __restrict__ x, const float* __restrict__ h,
                          const int* __restrict__ nodes) {
    int idx = blockIdx.x * 256 + threadIdx.x;
    if (idx >= CATP * Mm) return;
    int i = idx / Mm;
    int m = idx - i * Mm;
    float v = 0.0f;
    if (i < XC) {
        v = x[(size_t)nodes[m] * XC + i];
    } else if (i < INDIM) {
        int j = i - XC;
        v = g_r[(size_t)m * IS + j] * h[(size_t)nodes[m] * IS + j];
    }
    g_cnT[idx] = v;
}

// ---------------------------------------------------------------------------
// Candidate GEMM: BM=128, BN=128, BK=32. grid (1, 16, S_C), 256 thr, 8m x 8n.
// ---------------------------------------------------------------------------
__global__ __launch_bounds__(256, 2) void k_final(const float* __restrict__ q,
                                                  const float* __restrict__ Wc,
                                                  const float* __restrict__ bc) {
    __shared__ float qs[128][33];
    __shared__ float Zs[2][32][128];
    __shared__ float Wcs[2][32][128];  // row = 512B

    int t  = threadIdx.x;
    int m0 = blockIdx.y * 128;
    int n0 = 0;
    int s  = blockIdx.z;

#pragma unroll
    for (int p = 0; p < 16; p++) {
        int e = t + 256 * p;
        int m = e >> 5, d = e & 31;
        qs[m][d] = q[(size_t)(m0 + m) * QDIM + d];
    }
    __syncthreads();

    int tx = t & 15, ty = t >> 4;
    int mloc = t & 127;
    int kkb  = t >> 7;

    uint32_t wc_base = (uint32_t)__cvta_generic_to_shared(&Wcs[0][0][0]);

    ull acc[8][4];
#pragma unroll
    for (int r = 0; r < 8; r++)
#pragma unroll
        for (int j = 0; j < 4; j++) acc[r][j] = 0ULL;

    const int tbeg = (s * NT) / S_C;
    const int tend = ((s + 1) * NT) / S_C;
    const int nt_loc = tend - tbeg;
    float zreg[16];

#define CPA_WC(TILE, NB)                                                     \
    {                                                                        \
        int _tile = (TILE);                                                  \
        int _k0 = _tile * 32;                                                \
        _Pragma("unroll")                                                    \
        for (int p = 0; p < 4; p++) {                                        \
            int e = t + 256 * p;                                             \
            int row = e >> 5, c4 = e & 31;                                   \
            uint32_t off = (uint32_t)((NB) * 16384 + row * 512 + c4 * 16);   \
            if (_tile < 257)                                                 \
                cpa16(wc_base + off, &Wc[(size_t)(_k0 + row) * IS + c4 * 4]); \
            else                                                             \
                cpa16(wc_base + off, &bc[(size_t)row * IS + c4 * 4]);        \
        }                                                                    \
    }

    STAGE_Z(tbeg, g_cnT);
    CPA_WC(tbeg, 0);
    CP_COMMIT();
    STS_Z(0);
    CP_WAIT0();
    __syncthreads();

    for (int it = 0; it < nt_loc; it++) {
        int buf = it & 1, nb = buf ^ 1;
        bool has = (it + 1 < nt_loc);
        if (has) {
            STAGE_Z(tbeg + it + 1, g_cnT);
            CPA_WC(tbeg + it + 1, nb);
            CP_COMMIT();
        }
#pragma unroll
        for (int kk = 0; kk < 32; kk++) {
            float4 z0 = *(const float4*)&Zs[buf][kk][ty * 8];
            float4 z1 = *(const float4*)&Zs[buf][kk][ty * 8 + 4];
            ulonglong2 w0 = *(const ulonglong2*)&Wcs[buf][kk][tx * 8];
            ulonglong2 w1 = *(const ulonglong2*)&Wcs[buf][kk][tx * 8 + 4];
            float zv[8] = {z0.x, z0.y, z0.z, z0.w, z1.x, z1.y, z1.z, z1.w};
#pragma unroll
            for (int r = 0; r < 8; r++) {
                ull am = pack2(zv[r], zv[r]);
                fma2(acc[r][0], am, w0.x);
                fma2(acc[r][1], am, w0.y);
                fma2(acc[r][2], am, w1.x);
                fma2(acc[r][3], am, w1.y);
            }
        }
        if (has) {
            STS_Z(nb);
            CP_WAIT0();
        }
        __syncthreads();
    }

    float* dc = &g_pc[(size_t)s * Mm * IS];
#pragma unroll
    for (int r = 0; r < 8; r++) {
        int m = m0 + ty * 8 + r;
        float2 c0 = unpack2(acc[r][0]), c1 = unpack2(acc[r][1]);
        float2 c2 = unpack2(acc[r][2]), c3 = unpack2(acc[r][3]);
        *(float4*)&dc[(size_t)m * IS + tx * 8 + 0] = make_float4(c0.x, c0.y, c1.x, c1.y);
        *(float4*)&dc[(size_t)m * IS + tx * 8 + 4] = make_float4(c2.x, c2.y, c3.x, c3.y);
    }
#undef CPA_WC
#undef STAGE_Z
#undef STS_Z
#undef CPA_W
}

__global__ void k_final_reduce(const float* __restrict__ h,
                               const int* __restrict__ nodes,
                               float* __restrict__ out) {
    int idx = blockIdx.x * 256 + threadIdx.x;
    if (idx >= Mm * IS / 4) return;
    int m  = idx / (IS / 4);
    int c4 = idx - m * (IS / 4);
    int nm = nodes[m];

    const float4* pc = (const float4*)g_pc;
    float4 c = make_float4(0.f, 0.f, 0.f, 0.f);
#pragma unroll
    for (int s = 0; s < S_C; s++) {
        float4 a = pc[idx + (size_t)s * (Mm * IS / 4)];
        c.x += a.x; c.y += a.y; c.z += a.z; c.w += a.w;
    }
    float4 rr = ((const float4*)g_r)[idx];
    float4 uu = ((const float4*)g_u)[idx];
    float4 hv = *(const float4*)&h[(size_t)nm * IS + c4 * 4];
    float4 o;
    o.x = (1.0f - uu.x) * rr.x * hv.x + uu.x * tanhf(c.x);
    o.y = (1.0f - uu.y) * rr.y * hv.y + uu.y * tanhf(c.y);
    o.z = (1.0f - uu.z) * rr.z * hv.z + uu.z * tanhf(c.z);
    o.w = (1.0f - uu.w) * rr.w * hv.w + uu.w * tanhf(c.w);
    *(float4*)&out[(size_t)m * IS + c4 * 4] = o;
}

// ---------------------------------------------------------------------------
extern "C" void kernel_launch(void* const* d_in, const int* in_sizes, int n_in,
                              void* d_out, int out_size) {
    const float* x    = (const float*)d_in[0];
    const float* h    = (const float*)d_in[1];
    const float* q    = (const float*)d_in[2];
    const float* adj  = (const float*)d_in[3];
    const int*   nodes= (const int*)  d_in[4];
    const float* Wu   = (const float*)d_in[5];
    const float* bu   = (const float*)d_in[6];
    const float* Wr   = (const float*)d_in[7];
    const float* br   = (const float*)d_in[8];
    const float* Wc   = (const float*)d_in[9];
    const float* bc   = (const float*)d_in[10];
    float* out = (float*)d_out;

    k_pack_cat<<<(Nn * CATP + 255) / 256, 256>>>(x, h);
    k_gemm1<<<dim3(3, 16, S_G1), 256>>>(adj, nodes);
    k_g1_reduce<<<(CATP * Mm / 4 + 255) / 256, 256>>>();
    k_gates<<<dim3(2, 16, S_GATE), 256>>>(q, Wr, br, Wu, bu);
    k_gates_reduce<<<(Mm * IS / 4 + 255) / 256, 256>>>();
    k_pack_cn<<<(CATP * Mm + 255) / 256, 256>>>(x, h, nodes);
    k_final<<<dim3(1, 16, S_C), 256>>>(q, Wc, bc);
    k_final_reduce<<<(Mm * IS / 4 + 255) / 256, 256>>>(h, nodes, out);
}